// round 4
// baseline (speedup 1.0000x reference)
#include <cuda_runtime.h>
#include <cuda_bf16.h>
#include <cstddef>

// ---------------------------------------------------------------------------
// StockPredictor: 2-layer LSTM (B=256, T=2048, D=1, H1=128, H2=64) + FC head.
// R3: layer2 de-spilled (72 weight floats in regs + 24 in smem per thread),
// symmetric batch-split activation. Layer1 unchanged from R2.
// ---------------------------------------------------------------------------

constexpr int T  = 2048;
constexpr int B  = 256;
constexpr int H1 = 128;
constexpr int G1 = 4 * H1;   // 512
constexpr int H2 = 64;
constexpr int G2 = 4 * H2;   // 256
constexpr int BB = 2;        // batch elems per block
constexpr int NBLK = B / BB; // 128 blocks

// Layer-1 weight split: cols [0,64) in smem, cols [64,128) in registers
constexpr int W1S_COLS  = 64;
constexpr int W1S_PITCH = 68;    // 17*16B (odd) -> conflict-free LDS.128

constexpr int SMEM1_F = G1 * W1S_PITCH + BB * T + BB * H1 + BB * G1;
constexpr size_t SMEM1_B = SMEM1_F * sizeof(float);

// Layer-2: 72 weight floats in regs, 24 in smem per thread
constexpr int W2S_PITCH = 28;    // 24 floats + pad -> 7*16B (odd), conflict-free
constexpr int SMEM2_F = 2 * BB * H1   // h1 double buffer (512)
                      + BB * H2       // h2              (128)
                      + 2 * 2 * G2    // ps: 2 parts x G2 float2 (1024)
                      + BB * G2       // gates           (512)
                      + 2 * G2 * W2S_PITCH; // weights  (14336)
constexpr size_t SMEM2_B = SMEM2_F * sizeof(float);  // 66048 B

// scratch: h1 sequence, fp32  (256 MB)
__device__ float g_h1seq[(size_t)B * T * H1];

// ---------------------------------------------------------------------------
__device__ __forceinline__ void fma2(unsigned long long& acc,
                                     unsigned long long a,
                                     unsigned long long b) {
    asm("fma.rn.f32x2 %0, %1, %2, %0;" : "+l"(acc) : "l"(a), "l"(b));
}
__device__ __forceinline__ float f32x2_sum2(unsigned long long u,
                                            unsigned long long v) {
    unsigned long long s;
    asm("add.rn.f32x2 %0, %1, %2;" : "=l"(s) : "l"(u), "l"(v));
    float lo, hi;
    asm("mov.b64 {%0, %1}, %2;" : "=f"(lo), "=f"(hi) : "l"(s));
    return lo + hi;
}
__device__ __forceinline__ float sigmoid_fast(float x) {
    return __fdividef(1.0f, 1.0f + __expf(-x));
}
__device__ __forceinline__ float tanh_acc(float x) {
    return fmaf(2.0f, sigmoid_fast(2.0f * x), -1.0f);
}

// ---------------------------------------------------------------------------
// Layer 1: 512 threads, thread j owns gate row j of W_hh1 (full K=128).
// (unchanged from R2)
// ---------------------------------------------------------------------------
__global__ __launch_bounds__(512, 1)
void lstm1_kernel(const float* __restrict__ x,
                  const float* __restrict__ W_ih1,
                  const float* __restrict__ W_hh1,
                  const float* __restrict__ b_ih1,
                  const float* __restrict__ b_hh1)
{
    extern __shared__ float sm[];
    float* Ws = sm;                       // [512][W1S_PITCH], cols [0,64)
    float* xs = Ws + G1 * W1S_PITCH;      // [BB][T]
    float* hs = xs + BB * T;              // [BB][H1]
    float* gs = hs + BB * H1;             // [BB][G1] activated gates

    const int tid   = threadIdx.x;
    const int bbase = blockIdx.x * BB;

    for (int i = tid; i < G1 * W1S_COLS; i += 512) {
        int r = i >> 6;
        int c = i & 63;
        Ws[r * W1S_PITCH + c] = W_hh1[r * H1 + c];
    }
    ulonglong2 wr2[16];
    {
        const ulonglong2* wsrc =
            reinterpret_cast<const ulonglong2*>(W_hh1 + tid * H1 + W1S_COLS);
        #pragma unroll
        for (int j = 0; j < 16; j++) wr2[j] = wsrc[j];
    }

    const float wx   = W_ih1[tid];
    const float bias = b_ih1[tid] + b_hh1[tid];

    for (int i = tid; i < BB * T; i += 512)
        xs[i] = x[(size_t)bbase * T + i];
    if (tid < BB * H1) hs[tid] = 0.0f;
    __syncthreads();

    float c_state = 0.0f;  // valid for tid < 256

    const ulonglong2* w2  = reinterpret_cast<const ulonglong2*>(Ws + tid * W1S_PITCH);
    const ulonglong2* ha2 = reinterpret_cast<const ulonglong2*>(hs);
    const ulonglong2* hb2 = reinterpret_cast<const ulonglong2*>(hs + H1);

    for (int t = 0; t < T; t++) {
        unsigned long long a0 = 0, a1 = 0, c0 = 0, c1 = 0;

        #pragma unroll
        for (int i = 0; i < 16; i++) {   // smem-weight part, cols [0,64)
            ulonglong2 w = w2[i];
            ulonglong2 p = ha2[i];
            ulonglong2 q = hb2[i];
            fma2(a0, w.x, p.x); fma2(a1, w.y, p.y);
            fma2(c0, w.x, q.x); fma2(c1, w.y, q.y);
        }
        #pragma unroll
        for (int i = 0; i < 16; i++) {   // reg-weight part, cols [64,128)
            ulonglong2 w = wr2[i];
            ulonglong2 p = ha2[16 + i];
            ulonglong2 q = hb2[16 + i];
            fma2(a0, w.x, p.x); fma2(a1, w.y, p.y);
            fma2(c0, w.x, q.x); fma2(c1, w.y, q.y);
        }

        float acc0 = fmaf(xs[t],     wx, bias) + f32x2_sum2(a0, a1);
        float acc1 = fmaf(xs[T + t], wx, bias) + f32x2_sum2(c0, c1);

        float v0, v1;
        if (tid >= 2 * H1 && tid < 3 * H1) {       // g gate (warps 8-11)
            v0 = tanh_acc(acc0); v1 = tanh_acc(acc1);
        } else {
            v0 = sigmoid_fast(acc0); v1 = sigmoid_fast(acc1);
        }
        gs[tid]      = v0;
        gs[G1 + tid] = v1;
        __syncthreads();

        if (tid < BB * H1) {
            int bb = tid >> 7;
            int m  = tid & (H1 - 1);
            const float* gb = gs + bb * G1;
            float i_ = gb[m];
            float f_ = gb[H1 + m];
            float g_ = gb[2 * H1 + m];
            float o_ = gb[3 * H1 + m];
            c_state  = fmaf(f_, c_state, i_ * g_);
            float h  = o_ * tanh_acc(c_state);
            hs[tid]  = h;
            __stcs(&g_h1seq[((size_t)(bbase + bb) * T + t) * H1 + m], h);
        }
        __syncthreads();
    }
}

// ---------------------------------------------------------------------------
// Layer 2 + FC head: 512 threads. r = tid&255 gate row, part = tid>>8.
// part0: K = h1[0:96).  part1: K = h1[96:128) + h2[0:64).
// Per thread: 72 weight floats in regs (18 ulonglong2) + 24 in smem.
// ---------------------------------------------------------------------------
__global__ __launch_bounds__(512, 1)
void lstm2_kernel(const float* __restrict__ W_ih2,
                  const float* __restrict__ W_hh2,
                  const float* __restrict__ b_ih2,
                  const float* __restrict__ b_hh2,
                  const float* __restrict__ W_fc1,
                  const float* __restrict__ b_fc1,
                  const float* __restrict__ W_fc2,
                  const float* __restrict__ b_fc2,
                  float* __restrict__ out)
{
    extern __shared__ float sm[];
    float* h1s = sm;                 // [2][BB][H1] double buffer   (512)
    float* h2s = h1s + 2 * BB * H1;  // [BB][H2]                    (128)
    float* ps  = h2s + BB * H2;      // [2 parts][G2] float2        (1024)
    float* gs  = ps + 2 * 2 * G2;    // [BB][G2] activated gates    (512)
    float* Ws2 = gs + BB * G2;       // [512][W2S_PITCH] weights    (14336)

    const int tid   = threadIdx.x;
    const int r     = tid & (G2 - 1);
    const int part  = tid >> 8;
    const int bbase = blockIdx.x * BB;

    // --- smem weight tail: 24 floats per thread, row = tid ---
    {
        float* wrow = Ws2 + tid * W2S_PITCH;
        const float* src = (part == 0) ? (W_ih2 + r * H1 + 72)
                                       : (W_hh2 + r * H2 + 40);
        #pragma unroll
        for (int j = 0; j < 24; j++) wrow[j] = src[j];
    }

    // --- register weights: 72 floats = 18 ulonglong2 ---
    ulonglong2 wr2[18];
    if (part == 0) {
        // h1 cols [0,72)
        const ulonglong2* wsrc = reinterpret_cast<const ulonglong2*>(W_ih2 + r * H1);
        #pragma unroll
        for (int j = 0; j < 18; j++) wr2[j] = wsrc[j];
    } else {
        // h1 cols [96,128) + h2 cols [0,40)
        const ulonglong2* wa = reinterpret_cast<const ulonglong2*>(W_ih2 + r * H1 + 96);
        const ulonglong2* wb = reinterpret_cast<const ulonglong2*>(W_hh2 + r * H2);
        #pragma unroll
        for (int j = 0; j < 8; j++) wr2[j] = wa[j];
        #pragma unroll
        for (int j = 0; j < 10; j++) wr2[8 + j] = wb[j];
    }
    const float bias = b_ih2[r] + b_hh2[r];

    if (tid < BB * H2) h2s[tid] = 0.0f;
    if (tid < BB * H1) {   // preload h1 for t=0 into buffer 0
        int bb = tid >> 7, m = tid & (H1 - 1);
        h1s[tid] = __ldcs(&g_h1seq[((size_t)(bbase + bb) * T + 0) * H1 + m]);
    }
    __syncthreads();

    float c_state = 0.0f;  // valid for tid < 128

    const int ld_bb = (tid >> 7) & 1;        // for part1 prefetch (tid-256)
    const int ld_m  = tid & (H1 - 1);
    float2* psA = reinterpret_cast<float2*>(ps);
    float2* psB = psA + G2;
    const ulonglong2* ws2 =
        reinterpret_cast<const ulonglong2*>(Ws2 + tid * W2S_PITCH);

    for (int t = 0; t < T; t++) {
        const int cur = t & 1;
        const float* h1c = h1s + cur * BB * H1;

        float pre = 0.0f;
        if (part == 1 && t + 1 < T)
            pre = __ldcs(&g_h1seq[((size_t)(bbase + ld_bb) * T + (t + 1)) * H1 + ld_m]);

        unsigned long long a0 = 0, a1 = 0, c0 = 0, c1 = 0;
        if (part == 0) {
            const ulonglong2* pa = reinterpret_cast<const ulonglong2*>(h1c);
            const ulonglong2* pb = reinterpret_cast<const ulonglong2*>(h1c + H1);
            #pragma unroll
            for (int i = 0; i < 18; i++) {        // h1 cols [0,72) (regs)
                ulonglong2 w = wr2[i];
                ulonglong2 p = pa[i];
                ulonglong2 q = pb[i];
                fma2(a0, w.x, p.x); fma2(a1, w.y, p.y);
                fma2(c0, w.x, q.x); fma2(c1, w.y, q.y);
            }
            #pragma unroll
            for (int i = 0; i < 6; i++) {         // h1 cols [72,96) (smem)
                ulonglong2 w = ws2[i];
                ulonglong2 p = pa[18 + i];
                ulonglong2 q = pb[18 + i];
                fma2(a0, w.x, p.x); fma2(a1, w.y, p.y);
                fma2(c0, w.x, q.x); fma2(c1, w.y, q.y);
            }
        } else {
            const ulonglong2* pa = reinterpret_cast<const ulonglong2*>(h1c + 96);
            const ulonglong2* pb = reinterpret_cast<const ulonglong2*>(h1c + H1 + 96);
            #pragma unroll
            for (int i = 0; i < 8; i++) {         // h1 cols [96,128) (regs)
                ulonglong2 w = wr2[i];
                ulonglong2 p = pa[i];
                ulonglong2 q = pb[i];
                fma2(a0, w.x, p.x); fma2(a1, w.y, p.y);
                fma2(c0, w.x, q.x); fma2(c1, w.y, q.y);
            }
            const ulonglong2* va = reinterpret_cast<const ulonglong2*>(h2s);
            const ulonglong2* vb = reinterpret_cast<const ulonglong2*>(h2s + H2);
            #pragma unroll
            for (int i = 0; i < 10; i++) {        // h2 cols [0,40) (regs)
                ulonglong2 w = wr2[8 + i];
                ulonglong2 p = va[i];
                ulonglong2 q = vb[i];
                fma2(a0, w.x, p.x); fma2(a1, w.y, p.y);
                fma2(c0, w.x, q.x); fma2(c1, w.y, q.y);
            }
            #pragma unroll
            for (int i = 0; i < 6; i++) {         // h2 cols [40,64) (smem)
                ulonglong2 w = ws2[i];
                ulonglong2 p = va[10 + i];
                ulonglong2 q = vb[10 + i];
                fma2(a0, w.x, p.x); fma2(a1, w.y, p.y);
                fma2(c0, w.x, q.x); fma2(c1, w.y, q.y);
            }
        }
        float accb0 = f32x2_sum2(a0, a1);   // this part's partial, batch0
        float accb1 = f32x2_sum2(c0, c1);   // this part's partial, batch1

        if (part == 0) {
            psA[r] = make_float2(accb0, accb1);
        } else {
            psB[r] = make_float2(accb0, accb1);
            if (t + 1 < T) h1s[(cur ^ 1) * BB * H1 + (tid - G2)] = pre;
        }
        __syncthreads();

        // symmetric finalize: part p activates batch p
        {
            float2 pA = psA[r];
            float2 pB = psB[r];
            float tot = ((part == 0) ? (pA.x + pB.x) : (pA.y + pB.y)) + bias;
            float v;
            if (r >= 2 * H2 && r < 3 * H2) v = tanh_acc(tot);  // g gate
            else                           v = sigmoid_fast(tot);
            gs[part * G2 + r] = v;
        }
        __syncthreads();

        if (tid < BB * H2) {
            int bb = tid >> 6;
            int m  = tid & (H2 - 1);
            const float* gb = gs + bb * G2;
            float i_ = gb[m];
            float f_ = gb[H2 + m];
            float g_ = gb[2 * H2 + m];
            float o_ = gb[3 * H2 + m];
            c_state  = fmaf(f_, c_state, i_ * g_);
            h2s[tid] = o_ * tanh_acc(c_state);
        }
        __syncthreads();
    }

    // ---- FC head on final h2: [BB][64] -> [BB][25] -> [BB][1] ----
    if (tid < BB * 25) {
        int bb = tid / 25;
        int i  = tid - bb * 25;
        float a = b_fc1[i];
        #pragma unroll
        for (int k = 0; k < H2; k++)
            a = fmaf(W_fc1[i * H2 + k], h2s[bb * H2 + k], a);
        gs[bb * 32 + i] = a;
    }
    __syncthreads();
    if (tid < BB) {
        float a = b_fc2[0];
        #pragma unroll
        for (int i = 0; i < 25; i++)
            a = fmaf(W_fc2[i], gs[tid * 32 + i], a);
        out[bbase + tid] = a;
    }
}

// ---------------------------------------------------------------------------
extern "C" void kernel_launch(void* const* d_in, const int* in_sizes, int n_in,
                              void* d_out, int out_size)
{
    const float* x     = (const float*)d_in[0];
    const float* W_ih1 = (const float*)d_in[1];
    const float* W_hh1 = (const float*)d_in[2];
    const float* b_ih1 = (const float*)d_in[3];
    const float* b_hh1 = (const float*)d_in[4];
    const float* W_ih2 = (const float*)d_in[5];
    const float* W_hh2 = (const float*)d_in[6];
    const float* b_ih2 = (const float*)d_in[7];
    const float* b_hh2 = (const float*)d_in[8];
    const float* W_fc1 = (const float*)d_in[9];
    const float* b_fc1 = (const float*)d_in[10];
    const float* W_fc2 = (const float*)d_in[11];
    const float* b_fc2 = (const float*)d_in[12];
    float* out = (float*)d_out;

    static bool attr_done = false;
    if (!attr_done) {
        cudaFuncSetAttribute(lstm1_kernel,
                             cudaFuncAttributeMaxDynamicSharedMemorySize, (int)SMEM1_B);
        cudaFuncSetAttribute(lstm2_kernel,
                             cudaFuncAttributeMaxDynamicSharedMemorySize, (int)SMEM2_B);
        attr_done = true;
    }

    lstm1_kernel<<<NBLK, 512, SMEM1_B>>>(x, W_ih1, W_hh1, b_ih1, b_hh1);
    lstm2_kernel<<<NBLK, 512, SMEM2_B>>>(W_ih2, W_hh2, b_ih2, b_hh2,
                                         W_fc1, b_fc1, W_fc2, b_fc2, out);
}